// round 1
// baseline (speedup 1.0000x reference)
#include <cuda_runtime.h>
#include <math.h>

#define TABLE_SIZE 4194304          // 2^22
#define TABLE_MASK (TABLE_SIZE - 1)
#define NVOX (128*128*128)          // 2,097,152

// ---------------- device-global scratch (allocation-free) ----------------
__device__ double g_sum;
__device__ double g_sumsq;
__device__ float  g_mean;
__device__ float  g_inv_std;

// ---------------- stage 0: zero accumulators (graph replays!) ----------------
__global__ void zero_acc_kernel() {
    g_sum = 0.0;
    g_sumsq = 0.0;
}

// ---------------- stage 1: sum / sumsq over ht[0:3] (12.58M floats) ----------------
__global__ void reduce_kernel(const float4* __restrict__ p) {
    const int M4 = 3 * TABLE_SIZE / 4;
    double s = 0.0, ss = 0.0;
    int stride = gridDim.x * blockDim.x;
    for (int i = blockIdx.x * blockDim.x + threadIdx.x; i < M4; i += stride) {
        float4 v = p[i];
        s  += (double)v.x + (double)v.y + (double)v.z + (double)v.w;
        ss += (double)v.x * v.x + (double)v.y * v.y
            + (double)v.z * v.z + (double)v.w * v.w;
    }
    // warp reduce
    #pragma unroll
    for (int o = 16; o > 0; o >>= 1) {
        s  += __shfl_down_sync(0xffffffffu, s,  o);
        ss += __shfl_down_sync(0xffffffffu, ss, o);
    }
    __shared__ double sh_s[8], sh_ss[8];
    int w = threadIdx.x >> 5, l = threadIdx.x & 31;
    if (l == 0) { sh_s[w] = s; sh_ss[w] = ss; }
    __syncthreads();
    if (threadIdx.x == 0) {
        double ts = 0.0, tss = 0.0;
        int nw = blockDim.x >> 5;
        for (int k = 0; k < nw; k++) { ts += sh_s[k]; tss += sh_ss[k]; }
        atomicAdd(&g_sum, ts);
        atomicAdd(&g_sumsq, tss);
    }
}

// ---------------- stage 2: finalize mean / inv_std (ddof=1) ----------------
__global__ void finalize_kernel() {
    const double M = 3.0 * (double)TABLE_SIZE;
    double mean = g_sum / M;
    double var  = (g_sumsq - g_sum * g_sum / M) / (M - 1.0);
    g_mean    = (float)mean;
    g_inv_std = (float)(1.0 / sqrt(var));
}

// ---------------- stage 3: main per-voxel kernel ----------------
__device__ __forceinline__ float fsigmoid(float x) {
    return 1.0f / (1.0f + __expf(-x));
}

__global__ void __launch_bounds__(256)
voxel_kernel(const int*   __restrict__ coords,
             const float* __restrict__ ht,
             const float* __restrict__ cam,
             const float* __restrict__ far_p,
             const int*   __restrict__ vsz_p,
             float*       __restrict__ out)
{
    int i = blockIdx.x * blockDim.x + threadIdx.x;
    if (i >= NVOX) return;

    int cx = coords[3*i + 0];
    int cy = coords[3*i + 1];
    int cz = coords[3*i + 2];

    // hash index (primes: 1, 2654435761, 805459861), table size power of two
    unsigned h = (unsigned)cx ^ ((unsigned)cy * 2654435761u) ^ ((unsigned)cz * 805459861u);
    unsigned idx = h & TABLE_MASK;

    // gather 14 features (row 14 'curr' never reaches the output)
    float f[14];
    #pragma unroll
    for (int r = 0; r < 14; r++)
        f[r] = __ldg(ht + (size_t)r * TABLE_SIZE + idx);

    float far = __ldg(far_p);
    float vsz = vsz_p ? (float)__ldg(vsz_p) : 128.0f;
    float scale_fac = 2.0f * far / vsz;

    // dmeans: global normalize * scale_fac/6
    float k = g_inv_std * scale_fac * (1.0f / 6.0f);
    float mean = g_mean;
    float d0 = (f[0] - mean) * k;
    float d1 = (f[1] - mean) * k;
    float d2 = (f[2] - mean) * k;

    // voxel center + camera
    float inv_v = 1.0f / vsz;
    float off = far * inv_v - far;
    float m0 = d0 + (float)cx * inv_v * 2.0f * far + off + __ldg(cam + 0);
    float m1 = d1 + (float)cy * inv_v * 2.0f * far + off + __ldg(cam + 1);
    float m2 = d2 + (float)cz * inv_v * 2.0f * far + off + __ldg(cam + 2);

    // quaternion -> rotation
    float qr = f[3], qx = f[4], qy = f[5], qz = f[6];
    float qn = rsqrtf(qr*qr + qx*qx + qy*qy + qz*qz);
    qr *= qn; qx *= qn; qy *= qn; qz *= qn;

    float R00 = 1.0f - 2.0f*(qy*qy + qz*qz);
    float R01 = 2.0f*(qx*qy - qr*qz);
    float R02 = 2.0f*(qx*qz + qr*qy);
    float R10 = 2.0f*(qx*qy + qr*qz);
    float R11 = 1.0f - 2.0f*(qx*qx + qz*qz);
    float R12 = 2.0f*(qy*qz - qr*qx);
    float R20 = 2.0f*(qx*qz - qr*qy);
    float R21 = 2.0f*(qy*qz + qr*qx);
    float R22 = 1.0f - 2.0f*(qx*qx + qy*qy);

    // scales (sigmoid * scale_fac); cov = R diag(s^2) R^T
    float s0 = fsigmoid(f[7]) * scale_fac;
    float s1 = fsigmoid(f[8]) * scale_fac;
    float s2 = fsigmoid(f[9]) * scale_fac;
    float v0 = s0*s0, v1 = s1*s1, v2 = s2*s2;

    float c00 = R00*R00*v0 + R01*R01*v1 + R02*R02*v2;
    float c01 = R00*R10*v0 + R01*R11*v1 + R02*R12*v2;
    float c02 = R00*R20*v0 + R01*R21*v1 + R02*R22*v2;
    float c11 = R10*R10*v0 + R11*R11*v1 + R12*R12*v2;
    float c12 = R10*R20*v0 + R11*R21*v1 + R12*R22*v2;
    float c22 = R20*R20*v0 + R21*R21*v1 + R22*R22*v2;

    float sh0 = fsigmoid(f[10]);
    float sh1 = fsigmoid(f[11]);
    float sh2 = fsigmoid(f[12]);
    float op  = fsigmoid(f[13] - 4.0f);

    // output: [m0,m1,m2, c00,c01,c02,c10,c11,c12,c20,c21,c22, sh0,sh1,sh2, op]
    float4* o = (float4*)(out + (size_t)i * 16);
    o[0] = make_float4(m0,  m1,  m2,  c00);
    o[1] = make_float4(c01, c02, c01, c11);
    o[2] = make_float4(c12, c02, c12, c22);
    o[3] = make_float4(sh0, sh1, sh2, op);
}

// ---------------- launcher ----------------
extern "C" void kernel_launch(void* const* d_in, const int* in_sizes, int n_in,
                              void* d_out, int out_size)
{
    const int*   coords = (const int*)  d_in[0];
    const float* ht     = (const float*)d_in[1];
    const float* cam    = (const float*)d_in[2];
    const float* far_p  = (const float*)d_in[3];
    const int*   vsz_p  = (n_in >= 5) ? (const int*)d_in[4] : nullptr;
    float* out = (float*)d_out;

    zero_acc_kernel<<<1, 1>>>();
    reduce_kernel<<<2048, 256>>>((const float4*)ht);
    finalize_kernel<<<1, 1>>>();
    voxel_kernel<<<(NVOX + 255) / 256, 256>>>(coords, ht, cam, far_p, vsz_p, out);
}